// round 1
// baseline (speedup 1.0000x reference)
#include <cuda_runtime.h>
#include <math.h>
#include <stddef.h>

// Problem constants
constexpr int B_  = 16;
constexpr int C_  = 512;
constexpr int L_  = 1024;
constexpr int EC_ = 512;
constexpr int LE_ = 128;
constexpr int H_  = 8;
constexpr int G_  = 32;
constexpr int CH_ = C_ / H_;    // 64
constexpr int CPG = C_ / G_;    // 16

// Scratch (device globals; no dynamic allocation allowed)
__device__ float g_h[B_ * C_ * L_];              // 33.5 MB  groupnorm output
__device__ float g_qkv[B_ * 3 * C_ * L_];        // 100.7 MB qkv projections
__device__ float g_ekv[B_ * 2 * C_ * LE_];       // 8.4 MB   encoder kv
__device__ float g_a[B_ * C_ * L_];              // 33.5 MB  attention output

// ---------------------------------------------------------------------------
// GroupNorm: one block per (b, g). Group = 16 channels x 1024 = 16384 floats,
// contiguous in memory. Cache in smem, compute mean/var, normalize + affine.
// ---------------------------------------------------------------------------
__global__ __launch_bounds__(256) void gn_kernel(
    const float* __restrict__ x, const float* __restrict__ sc,
    const float* __restrict__ bi, float* __restrict__ h)
{
    extern __shared__ float buf[];     // 16384 floats (64 KB)
    __shared__ float red[64];
    int b = blockIdx.x >> 5, g = blockIdx.x & 31;
    size_t base = ((size_t)b * C_ + (size_t)g * CPG) * L_;
    const float4* xp = (const float4*)(x + base);
    float4* hp = (float4*)(h + base);

    float s = 0.f, s2 = 0.f;
    for (int i = threadIdx.x; i < CPG * L_ / 4; i += 256) {
        float4 v = xp[i];
        ((float4*)buf)[i] = v;
        s  += v.x + v.y + v.z + v.w;
        s2 += v.x * v.x + v.y * v.y + v.z * v.z + v.w * v.w;
    }
    #pragma unroll
    for (int d = 16; d; d >>= 1) {
        s  += __shfl_xor_sync(0xffffffffu, s, d);
        s2 += __shfl_xor_sync(0xffffffffu, s2, d);
    }
    int warp = threadIdx.x >> 5;
    if ((threadIdx.x & 31) == 0) { red[warp] = s; red[32 + warp] = s2; }
    __syncthreads();
    if (threadIdx.x < 32) {
        s  = (threadIdx.x < 8) ? red[threadIdx.x] : 0.f;
        s2 = (threadIdx.x < 8) ? red[32 + threadIdx.x] : 0.f;
        #pragma unroll
        for (int d = 4; d; d >>= 1) {
            s  += __shfl_xor_sync(0xffffffffu, s, d);
            s2 += __shfl_xor_sync(0xffffffffu, s2, d);
        }
        if (threadIdx.x == 0) { red[0] = s; red[1] = s2; }
    }
    __syncthreads();
    const float inv_n = 1.f / (float)(CPG * L_);
    float mean = red[0] * inv_n;
    float var  = red[1] * inv_n - mean * mean;
    float rstd = rsqrtf(var + 1e-5f);
    for (int i = threadIdx.x; i < CPG * L_ / 4; i += 256) {
        int c = g * CPG + (i >> 8);      // (i*4)/1024
        float a  = sc[c] * rstd;
        float bb = bi[c] - mean * a;
        float4 v = ((float4*)buf)[i];
        v.x = v.x * a + bb; v.y = v.y * a + bb;
        v.z = v.z * a + bb; v.w = v.w * a + bb;
        hp[i] = v;
    }
}

// ---------------------------------------------------------------------------
// Batched SGEMM: C[z] = A(MxK, shared weights) * B[z](KxN) + bias, optional
// residual add. 128x128 block tile, BK=8, 256 threads, 8x8 per thread.
// All dims divide tile sizes exactly for this problem.
// ---------------------------------------------------------------------------
template<bool RES>
__global__ __launch_bounds__(256) void gemm_kernel(
    const float* __restrict__ A, const float* __restrict__ Bm,
    const float* __restrict__ bias, const float* __restrict__ res,
    float* __restrict__ Cm, int M, int N, int K)
{
    __shared__ float As[8][128];
    __shared__ float Bs[8][128];
    int tid = threadIdx.x;
    int tx = tid & 15, ty = tid >> 4;
    int m0 = blockIdx.y * 128, n0 = blockIdx.x * 128;
    const float* Bp = Bm + (size_t)blockIdx.z * K * N;
    float* Cp = Cm + (size_t)blockIdx.z * M * N;

    int arow = tid >> 1, acol = (tid & 1) * 4;
    int brow = tid >> 5, bcol = (tid & 31) * 4;
    const float* Ap  = A  + (size_t)(m0 + arow) * K + acol;
    const float* Bpp = Bp + (size_t)brow * N + n0 + bcol;

    float acc[8][8] = {};
    for (int k0 = 0; k0 < K; k0 += 8) {
        float4 a4 = *(const float4*)(Ap + k0);
        float4 b4 = *(const float4*)(Bpp + (size_t)k0 * N);
        As[acol + 0][arow] = a4.x;
        As[acol + 1][arow] = a4.y;
        As[acol + 2][arow] = a4.z;
        As[acol + 3][arow] = a4.w;
        *(float4*)&Bs[brow][bcol] = b4;
        __syncthreads();
        #pragma unroll
        for (int kk = 0; kk < 8; kk++) {
            float av[8], bv[8];
            *(float4*)&av[0] = *(float4*)&As[kk][ty * 8];
            *(float4*)&av[4] = *(float4*)&As[kk][ty * 8 + 4];
            *(float4*)&bv[0] = *(float4*)&Bs[kk][tx * 8];
            *(float4*)&bv[4] = *(float4*)&Bs[kk][tx * 8 + 4];
            #pragma unroll
            for (int i = 0; i < 8; i++)
                #pragma unroll
                for (int j = 0; j < 8; j++)
                    acc[i][j] += av[i] * bv[j];
        }
        __syncthreads();
    }
    #pragma unroll
    for (int i = 0; i < 8; i++) {
        int m = m0 + ty * 8 + i;
        float bv = bias[m];
        size_t off = (size_t)m * N + n0 + tx * 8;
        float4 o0, o1;
        o0.x = acc[i][0] + bv; o0.y = acc[i][1] + bv;
        o0.z = acc[i][2] + bv; o0.w = acc[i][3] + bv;
        o1.x = acc[i][4] + bv; o1.y = acc[i][5] + bv;
        o1.z = acc[i][6] + bv; o1.w = acc[i][7] + bv;
        if (RES) {
            const float* rrow = res + (size_t)blockIdx.z * M * N + off;
            float4 r0 = *(const float4*)rrow;
            float4 r1 = *(const float4*)(rrow + 4);
            o0.x += r0.x; o0.y += r0.y; o0.z += r0.z; o0.w += r0.w;
            o1.x += r1.x; o1.y += r1.y; o1.z += r1.z; o1.w += r1.w;
        }
        *(float4*)(Cp + off)     = o0;
        *(float4*)(Cp + off + 4) = o1;
    }
}

// ---------------------------------------------------------------------------
// Flash attention: grid (L/64 t-tiles, B*H heads), 256 threads (16x16).
// q tile [64c x 64t] in smem; loop 18 chunks of 64 keys; online softmax.
// k/v come from ekv (first 128 keys) then qkv (next 1024) -- chunks never
// straddle the boundary (128 = 2*64).
// Combined scale: (q*s)·(k*s) = q·k / sqrt(ch) = q·k * 0.125.
// ---------------------------------------------------------------------------
constexpr int ATTN_PAD = 68;
constexpr int ATTN_SMEM_BYTES = 4 * 64 * ATTN_PAD * 4;   // 69632

__global__ __launch_bounds__(256) void attn_kernel(
    const float* __restrict__ qkv, const float* __restrict__ ekv,
    float* __restrict__ outa)
{
    extern __shared__ float sm[];
    float* qs  = sm;                     // [c][t], stride 68
    float* ks  = sm + 64 * ATTN_PAD;     // [c][s], stride 68
    float* vst = sm + 2 * 64 * ATTN_PAD; // [s][c], stride 68 (transposed)
    float* ps  = sm + 3 * 64 * ATTN_PAD; // [t][s], stride 68

    int tid = threadIdx.x;
    int tx = tid & 15, ty = tid >> 4;
    int t0 = blockIdx.x * 64;
    int bh = blockIdx.y;
    int b = bh >> 3, hh = bh & 7;

    const float* qp  = qkv + ((size_t)b * (3 * C_) + (size_t)hh * (3 * CH_)) * L_;
    const float* kqp = qp + (size_t)CH_ * L_;
    const float* vqp = qp + (size_t)2 * CH_ * L_;
    const float* ekp = ekv + ((size_t)b * (2 * C_) + (size_t)hh * (2 * CH_)) * LE_;
    const float* evp = ekp + (size_t)CH_ * LE_;

    // Load q tile (64 ch x 64 t), pre-scaled by 1/8
    #pragma unroll
    for (int i = 0; i < 4; i++) {
        int f = tid + 256 * i;           // float4 index, 1024 total
        int row = f >> 4, col = (f & 15) * 4;
        float4 v = *(const float4*)(qp + (size_t)row * L_ + t0 + col);
        v.x *= 0.125f; v.y *= 0.125f; v.z *= 0.125f; v.w *= 0.125f;
        *(float4*)&qs[row * ATTN_PAD + col] = v;
    }

    float m_i[4], l_i[4], o[4][4];
    #pragma unroll
    for (int i = 0; i < 4; i++) {
        m_i[i] = -1e30f; l_i[i] = 0.f;
        #pragma unroll
        for (int j = 0; j < 4; j++) o[i][j] = 0.f;
    }

    for (int cidx = 0; cidx < (LE_ + L_) / 64; cidx++) {
        int s0 = cidx * 64;
        const float* kp; const float* vp; int ld, off;
        if (s0 < LE_) { kp = ekp; vp = evp; ld = LE_; off = s0; }
        else          { kp = kqp; vp = vqp; ld = L_;  off = s0 - LE_; }

        __syncthreads();   // previous iteration fully consumed ks/vst/ps
        #pragma unroll
        for (int i = 0; i < 4; i++) {
            int f = tid + 256 * i;
            int row = f >> 4, col = (f & 15) * 4;
            float4 kv = *(const float4*)(kp + (size_t)row * ld + off + col);
            *(float4*)&ks[row * ATTN_PAD + col] = kv;
            float4 vv = *(const float4*)(vp + (size_t)row * ld + off + col);
            vst[(col + 0) * ATTN_PAD + row] = vv.x;
            vst[(col + 1) * ATTN_PAD + row] = vv.y;
            vst[(col + 2) * ATTN_PAD + row] = vv.z;
            vst[(col + 3) * ATTN_PAD + row] = vv.w;
        }
        __syncthreads();

        // S = q^T k  (4x4 per thread)
        float sacc[4][4] = {};
        #pragma unroll 8
        for (int c = 0; c < 64; c++) {
            float4 q4 = *(float4*)&qs[c * ATTN_PAD + ty * 4];
            float4 k4 = *(float4*)&ks[c * ATTN_PAD + tx * 4];
            sacc[0][0] += q4.x * k4.x; sacc[0][1] += q4.x * k4.y;
            sacc[0][2] += q4.x * k4.z; sacc[0][3] += q4.x * k4.w;
            sacc[1][0] += q4.y * k4.x; sacc[1][1] += q4.y * k4.y;
            sacc[1][2] += q4.y * k4.z; sacc[1][3] += q4.y * k4.w;
            sacc[2][0] += q4.z * k4.x; sacc[2][1] += q4.z * k4.y;
            sacc[2][2] += q4.z * k4.z; sacc[2][3] += q4.z * k4.w;
            sacc[3][0] += q4.w * k4.x; sacc[3][1] += q4.w * k4.y;
            sacc[3][2] += q4.w * k4.z; sacc[3][3] += q4.w * k4.w;
        }

        // Online softmax per row (reduce across 16 lanes of the half-warp)
        #pragma unroll
        for (int i = 0; i < 4; i++) {
            float rmax = fmaxf(fmaxf(sacc[i][0], sacc[i][1]),
                               fmaxf(sacc[i][2], sacc[i][3]));
            #pragma unroll
            for (int d = 1; d < 16; d <<= 1)
                rmax = fmaxf(rmax, __shfl_xor_sync(0xffffffffu, rmax, d));
            float mn = fmaxf(m_i[i], rmax);
            float alpha = __expf(m_i[i] - mn);
            float p0 = __expf(sacc[i][0] - mn);
            float p1 = __expf(sacc[i][1] - mn);
            float p2 = __expf(sacc[i][2] - mn);
            float p3 = __expf(sacc[i][3] - mn);
            float rs = p0 + p1 + p2 + p3;
            #pragma unroll
            for (int d = 1; d < 16; d <<= 1)
                rs += __shfl_xor_sync(0xffffffffu, rs, d);
            l_i[i] = l_i[i] * alpha + rs;
            m_i[i] = mn;
            o[i][0] *= alpha; o[i][1] *= alpha;
            o[i][2] *= alpha; o[i][3] *= alpha;
            float4 pv = make_float4(p0, p1, p2, p3);
            *(float4*)&ps[(ty * 4 + i) * ATTN_PAD + tx * 4] = pv;
        }
        __syncthreads();

        // O += P @ V^T  (4x4 per thread, output cols = channels)
        #pragma unroll 8
        for (int s = 0; s < 64; s++) {
            float4 v4 = *(float4*)&vst[s * ATTN_PAD + tx * 4];
            float pr0 = ps[(ty * 4 + 0) * ATTN_PAD + s];
            float pr1 = ps[(ty * 4 + 1) * ATTN_PAD + s];
            float pr2 = ps[(ty * 4 + 2) * ATTN_PAD + s];
            float pr3 = ps[(ty * 4 + 3) * ATTN_PAD + s];
            o[0][0] += pr0 * v4.x; o[0][1] += pr0 * v4.y;
            o[0][2] += pr0 * v4.z; o[0][3] += pr0 * v4.w;
            o[1][0] += pr1 * v4.x; o[1][1] += pr1 * v4.y;
            o[1][2] += pr1 * v4.z; o[1][3] += pr1 * v4.w;
            o[2][0] += pr2 * v4.x; o[2][1] += pr2 * v4.y;
            o[2][2] += pr2 * v4.z; o[2][3] += pr2 * v4.w;
            o[3][0] += pr3 * v4.x; o[3][1] += pr3 * v4.y;
            o[3][2] += pr3 * v4.z; o[3][3] += pr3 * v4.w;
        }
    }

    // Write a[b, hh*64 + c, t0 + t]
    size_t obase = (size_t)b * C_ * L_ + (size_t)(hh * CH_) * L_ + t0;
    #pragma unroll
    for (int i = 0; i < 4; i++) {
        float inv = 1.f / l_i[i];
        int t = ty * 4 + i;
        #pragma unroll
        for (int j = 0; j < 4; j++) {
            int c = tx * 4 + j;
            outa[obase + (size_t)c * L_ + t] = o[i][j] * inv;
        }
    }
}

// ---------------------------------------------------------------------------
// Launch
// ---------------------------------------------------------------------------
extern "C" void kernel_launch(void* const* d_in, const int* in_sizes, int n_in,
                              void* d_out, int out_size)
{
    const float* x      = (const float*)d_in[0];
    const float* enc    = (const float*)d_in[1];
    const float* gnsc   = (const float*)d_in[2];
    const float* gnbi   = (const float*)d_in[3];
    const float* w_qkv  = (const float*)d_in[4];
    const float* b_qkv  = (const float*)d_in[5];
    const float* w_ekv  = (const float*)d_in[6];
    const float* b_ekv  = (const float*)d_in[7];
    const float* w_proj = (const float*)d_in[8];
    const float* b_proj = (const float*)d_in[9];
    float* out = (float*)d_out;

    float *h, *qkv, *ekvb, *a;
    cudaGetSymbolAddress((void**)&h,    g_h);
    cudaGetSymbolAddress((void**)&qkv,  g_qkv);
    cudaGetSymbolAddress((void**)&ekvb, g_ekv);
    cudaGetSymbolAddress((void**)&a,    g_a);

    const int GN_SMEM = CPG * L_ * 4;   // 65536
    cudaFuncSetAttribute(gn_kernel, cudaFuncAttributeMaxDynamicSharedMemorySize, GN_SMEM);
    cudaFuncSetAttribute(attn_kernel, cudaFuncAttributeMaxDynamicSharedMemorySize, ATTN_SMEM_BYTES);

    // 1. GroupNorm
    gn_kernel<<<B_ * G_, 256, GN_SMEM>>>(x, gnsc, gnbi, h);

    // 2. qkv = w_qkv @ h + b_qkv   (M=1536, N=1024, K=512, batch 16)
    gemm_kernel<false><<<dim3(L_ / 128, 3 * C_ / 128, B_), 256>>>(
        w_qkv, h, b_qkv, nullptr, qkv, 3 * C_, L_, C_);

    // 3. ekv = w_ekv @ enc + b_ekv (M=1024, N=128, K=512, batch 16)
    gemm_kernel<false><<<dim3(LE_ / 128, 2 * C_ / 128, B_), 256>>>(
        w_ekv, enc, b_ekv, nullptr, ekvb, 2 * C_, LE_, EC_);

    // 4. attention -> a (B, C, L)
    attn_kernel<<<dim3(L_ / 64, B_ * H_), 256, ATTN_SMEM_BYTES>>>(qkv, ekvb, a);

    // 5. out = x + w_proj @ a + b_proj (M=512, N=1024, K=512, batch 16)
    gemm_kernel<true><<<dim3(L_ / 128, C_ / 128, B_), 256>>>(
        w_proj, a, b_proj, x, out, C_, L_, C_);
}

// round 2
// speedup vs baseline: 3.3265x; 3.3265x over previous
#include <cuda_runtime.h>
#include <cuda_bf16.h>
#include <math.h>
#include <stddef.h>
#include <stdint.h>

// Problem constants
constexpr int B_  = 16;
constexpr int C_  = 512;
constexpr int L_  = 1024;
constexpr int EC_ = 512;
constexpr int LE_ = 128;
constexpr int H_  = 8;
constexpr int G_  = 32;
constexpr int CH_ = C_ / H_;    // 64
constexpr int CPG = C_ / G_;    // 16

// Scratch (device globals; no dynamic allocation allowed)
__device__ float g_h[B_ * C_ * L_];
__device__ float g_qkv[B_ * 3 * C_ * L_];
__device__ float g_ekv[B_ * 2 * C_ * LE_];
__device__ float g_a[B_ * C_ * L_];

// ---------------------------------------------------------------------------
// MMA helpers
// ---------------------------------------------------------------------------
__device__ __forceinline__ uint32_t f2tf(float x) {
    uint32_t r; asm("cvt.rna.tf32.f32 %0, %1;\n" : "=r"(r) : "f"(x)); return r;
}
__device__ __forceinline__ uint32_t packbf(float lo, float hi) {
    __nv_bfloat162 h = __floats2bfloat162_rn(lo, hi);   // x=lo, y=hi
    return *reinterpret_cast<uint32_t*>(&h);
}
__device__ __forceinline__ void mma_tf32(float* d, const uint32_t* a, const uint32_t* b) {
    asm volatile("mma.sync.aligned.m16n8k8.row.col.f32.tf32.tf32.f32 "
        "{%0,%1,%2,%3},{%4,%5,%6,%7},{%8,%9},{%0,%1,%2,%3};\n"
        : "+f"(d[0]), "+f"(d[1]), "+f"(d[2]), "+f"(d[3])
        : "r"(a[0]), "r"(a[1]), "r"(a[2]), "r"(a[3]), "r"(b[0]), "r"(b[1]));
}
__device__ __forceinline__ void mma_bf16(float* d, const uint32_t* a, const uint32_t* b) {
    asm volatile("mma.sync.aligned.m16n8k16.row.col.f32.bf16.bf16.f32 "
        "{%0,%1,%2,%3},{%4,%5,%6,%7},{%8,%9},{%0,%1,%2,%3};\n"
        : "+f"(d[0]), "+f"(d[1]), "+f"(d[2]), "+f"(d[3])
        : "r"(a[0]), "r"(a[1]), "r"(a[2]), "r"(a[3]), "r"(b[0]), "r"(b[1]));
}

// ---------------------------------------------------------------------------
// GroupNorm: one block per (b, g). Group cached in smem (single global read).
// ---------------------------------------------------------------------------
__global__ __launch_bounds__(256) void gn_kernel(
    const float* __restrict__ x, const float* __restrict__ sc,
    const float* __restrict__ bi, float* __restrict__ h)
{
    extern __shared__ float buf[];     // 16384 floats (64 KB)
    __shared__ float red[64];
    int b = blockIdx.x >> 5, g = blockIdx.x & 31;
    size_t base = ((size_t)b * C_ + (size_t)g * CPG) * L_;
    const float4* xp = (const float4*)(x + base);
    float4* hp = (float4*)(h + base);

    float s = 0.f, s2 = 0.f;
    for (int i = threadIdx.x; i < CPG * L_ / 4; i += 256) {
        float4 v = xp[i];
        ((float4*)buf)[i] = v;
        s  += v.x + v.y + v.z + v.w;
        s2 += v.x * v.x + v.y * v.y + v.z * v.z + v.w * v.w;
    }
    #pragma unroll
    for (int d = 16; d; d >>= 1) {
        s  += __shfl_xor_sync(0xffffffffu, s, d);
        s2 += __shfl_xor_sync(0xffffffffu, s2, d);
    }
    int warp = threadIdx.x >> 5;
    if ((threadIdx.x & 31) == 0) { red[warp] = s; red[32 + warp] = s2; }
    __syncthreads();
    if (threadIdx.x < 32) {
        s  = (threadIdx.x < 8) ? red[threadIdx.x] : 0.f;
        s2 = (threadIdx.x < 8) ? red[32 + threadIdx.x] : 0.f;
        #pragma unroll
        for (int d = 4; d; d >>= 1) {
            s  += __shfl_xor_sync(0xffffffffu, s, d);
            s2 += __shfl_xor_sync(0xffffffffu, s2, d);
        }
        if (threadIdx.x == 0) { red[0] = s; red[1] = s2; }
    }
    __syncthreads();
    const float inv_n = 1.f / (float)(CPG * L_);
    float mean = red[0] * inv_n;
    float var  = red[1] * inv_n - mean * mean;
    float rstd = rsqrtf(var + 1e-5f);
    for (int i = threadIdx.x; i < CPG * L_ / 4; i += 256) {
        int c = g * CPG + (i >> 8);
        float a  = sc[c] * rstd;
        float bb = bi[c] - mean * a;
        float4 v = ((float4*)buf)[i];
        v.x = v.x * a + bb; v.y = v.y * a + bb;
        v.z = v.z * a + bb; v.w = v.w * a + bb;
        hp[i] = v;
    }
}

// ---------------------------------------------------------------------------
// TF32 tensor-core batched GEMM: C[z] = A(MxK, shared) * B[z](KxN) + bias
// (+ optional residual). 128x128 block tile, k-chunk 32, 256 threads = 8 warps
// in 4(m) x 2(n); warp tile 32x64 (2 m16-tiles x 8 n8-tiles).
// ---------------------------------------------------------------------------
constexpr int AP = 36;    // As pad: banks (4*row + k) conflict-free
constexpr int BP = 136;   // Bs pad: banks (8*k + n) conflict-free

template<bool RES>
__global__ __launch_bounds__(256) void gemm_tc(
    const float* __restrict__ A, const float* __restrict__ Bm,
    const float* __restrict__ bias, const float* __restrict__ res,
    float* __restrict__ Cm, int M, int N, int K)
{
    __shared__ float As[128 * AP];
    __shared__ float Bs[32 * BP];
    int tid = threadIdx.x, lane = tid & 31, warp = tid >> 5;
    int g = lane >> 2, tg = lane & 3;
    int wm = warp >> 1, wn = warp & 1;
    int m0 = blockIdx.y * 128, n0 = blockIdx.x * 128;
    const float* Bp = Bm + (size_t)blockIdx.z * K * N;

    float acc[2][8][4];
    #pragma unroll
    for (int i = 0; i < 2; i++)
        #pragma unroll
        for (int j = 0; j < 8; j++)
            #pragma unroll
            for (int r = 0; r < 4; r++) acc[i][j][r] = 0.f;

    for (int k0 = 0; k0 < K; k0 += 32) {
        __syncthreads();
        // A tile 128x32 -> As[row][k] (tf32)
        #pragma unroll
        for (int i = 0; i < 4; i++) {
            int f = tid + 256 * i, row = f >> 3, k4 = (f & 7) * 4;
            float4 v = *(const float4*)(A + (size_t)(m0 + row) * K + k0 + k4);
            float4 w;
            w.x = __uint_as_float(f2tf(v.x)); w.y = __uint_as_float(f2tf(v.y));
            w.z = __uint_as_float(f2tf(v.z)); w.w = __uint_as_float(f2tf(v.w));
            *(float4*)(As + row * AP + k4) = w;
        }
        // B tile 32x128 -> Bs[k][n] (tf32)
        #pragma unroll
        for (int i = 0; i < 4; i++) {
            int f = tid + 256 * i, row = f >> 5, n4 = (f & 31) * 4;
            float4 v = *(const float4*)(Bp + (size_t)(k0 + row) * N + n0 + n4);
            float4 w;
            w.x = __uint_as_float(f2tf(v.x)); w.y = __uint_as_float(f2tf(v.y));
            w.z = __uint_as_float(f2tf(v.z)); w.w = __uint_as_float(f2tf(v.w));
            *(float4*)(Bs + row * BP + n4) = w;
        }
        __syncthreads();

        const uint32_t* Au = (const uint32_t*)As;
        const uint32_t* Bu = (const uint32_t*)Bs;
        #pragma unroll
        for (int k8 = 0; k8 < 4; k8++) {
            uint32_t af[2][4], bf2[8][2];
            #pragma unroll
            for (int mt = 0; mt < 2; mt++) {
                int r = wm * 32 + mt * 16 + g;
                af[mt][0] = Au[r * AP + k8 * 8 + tg];
                af[mt][1] = Au[(r + 8) * AP + k8 * 8 + tg];
                af[mt][2] = Au[r * AP + k8 * 8 + tg + 4];
                af[mt][3] = Au[(r + 8) * AP + k8 * 8 + tg + 4];
            }
            #pragma unroll
            for (int nt = 0; nt < 8; nt++) {
                int c = wn * 64 + nt * 8 + g;
                bf2[nt][0] = Bu[(k8 * 8 + tg) * BP + c];
                bf2[nt][1] = Bu[(k8 * 8 + tg + 4) * BP + c];
            }
            #pragma unroll
            for (int mt = 0; mt < 2; mt++)
                #pragma unroll
                for (int nt = 0; nt < 8; nt++)
                    mma_tf32(acc[mt][nt], af[mt], bf2[nt]);
        }
    }

    // Epilogue
    float* Cp = Cm + (size_t)blockIdx.z * M * N;
    const float* Rp = RES ? (res + (size_t)blockIdx.z * M * N) : nullptr;
    #pragma unroll
    for (int mt = 0; mt < 2; mt++) {
        int r0 = m0 + wm * 32 + mt * 16 + g;
        float bv0 = bias[r0], bv1 = bias[r0 + 8];
        #pragma unroll
        for (int nt = 0; nt < 8; nt++) {
            int c = n0 + wn * 64 + nt * 8 + 2 * tg;
            float2 v0 = make_float2(acc[mt][nt][0] + bv0, acc[mt][nt][1] + bv0);
            float2 v1 = make_float2(acc[mt][nt][2] + bv1, acc[mt][nt][3] + bv1);
            size_t o0 = (size_t)r0 * N + c;
            size_t o1 = (size_t)(r0 + 8) * N + c;
            if (RES) {
                float2 r0v = *(const float2*)(Rp + o0);
                float2 r1v = *(const float2*)(Rp + o1);
                v0.x += r0v.x; v0.y += r0v.y;
                v1.x += r1v.x; v1.y += r1v.y;
            }
            *(float2*)(Cp + o0) = v0;
            *(float2*)(Cp + o1) = v1;
        }
    }
}

// ---------------------------------------------------------------------------
// Flash attention with tensor cores.
// Grid (L/64 t-tiles, B*H heads), 128 threads = 4 warps; warp = 16 q-rows.
// S = Q^T K (TF32 mma, q pre-scaled 1/8); online softmax in accum layout;
// P reused directly as bf16 A-fragments of m16n8k16; V transposed + packed
// to bf16 pairs at load time so B-fragments are single 32-bit LDS.
// ---------------------------------------------------------------------------
constexpr int QP = 68;   // qs[t][c]  banks 4t+c-lane pattern conflict-free
constexpr int KP = 72;   // ks[c][s]  banks 8c+s
constexpr int VP = 72;   // vsp[s2][c] banks 8s2+c

__global__ __launch_bounds__(128) void attn_tc(
    const float* __restrict__ qkv, const float* __restrict__ ekv,
    float* __restrict__ outa)
{
    __shared__ float    qs[64 * QP];      // Q^T tile [t][c], tf32 (reused as osm)
    __shared__ float    ks[64 * KP];      // K tile [c][s], tf32
    __shared__ uint32_t vsp[32 * VP];     // V^T tile as bf16 pairs [s/2][c]

    int tid = threadIdx.x, lane = tid & 31, warp = tid >> 5;
    int g = lane >> 2, tg = lane & 3;
    int t0 = blockIdx.x * 64;
    int bh = blockIdx.y, b = bh >> 3, hh = bh & 7;

    const float* qp  = qkv + ((size_t)b * (3 * C_) + (size_t)hh * (3 * CH_)) * L_;
    const float* kqp = qp + (size_t)CH_ * L_;
    const float* vqp = qp + (size_t)2 * CH_ * L_;
    const float* ekp = ekv + ((size_t)b * (2 * C_) + (size_t)hh * (2 * CH_)) * LE_;
    const float* evp = ekp + (size_t)CH_ * LE_;

    // Load Q tile transposed into qs[t][c], scaled 1/8, tf32
    #pragma unroll
    for (int i = 0; i < 8; i++) {
        int f = tid + 128 * i, c = f >> 4, t4 = (f & 15) * 4;
        float4 v = *(const float4*)(qp + (size_t)c * L_ + t0 + t4);
        qs[(t4 + 0) * QP + c] = __uint_as_float(f2tf(v.x * 0.125f));
        qs[(t4 + 1) * QP + c] = __uint_as_float(f2tf(v.y * 0.125f));
        qs[(t4 + 2) * QP + c] = __uint_as_float(f2tf(v.z * 0.125f));
        qs[(t4 + 3) * QP + c] = __uint_as_float(f2tf(v.w * 0.125f));
    }

    float m_i[2] = {-1e30f, -1e30f}, l_i[2] = {0.f, 0.f};
    float Oacc[8][4];
    #pragma unroll
    for (int i = 0; i < 8; i++)
        #pragma unroll
        for (int r = 0; r < 4; r++) Oacc[i][r] = 0.f;

    for (int ci = 0; ci < (LE_ + L_) / 64; ci++) {
        int s0 = ci * 64;
        const float* kp; const float* vp; int ld, off;
        if (s0 < LE_) { kp = ekp; vp = evp; ld = LE_; off = s0; }
        else          { kp = kqp; vp = vqp; ld = L_;  off = s0 - LE_; }

        __syncthreads();   // previous chunk fully consumed
        #pragma unroll
        for (int i = 0; i < 8; i++) {
            int f = tid + 128 * i, c = f >> 4, s4 = (f & 15) * 4;
            float4 kv = *(const float4*)(kp + (size_t)c * ld + off + s4);
            float4 kw;
            kw.x = __uint_as_float(f2tf(kv.x)); kw.y = __uint_as_float(f2tf(kv.y));
            kw.z = __uint_as_float(f2tf(kv.z)); kw.w = __uint_as_float(f2tf(kv.w));
            *(float4*)(ks + c * KP + s4) = kw;
            float4 vv = *(const float4*)(vp + (size_t)c * ld + off + s4);
            vsp[(s4 >> 1) * VP + c]       = packbf(vv.x, vv.y);
            vsp[((s4 >> 1) + 1) * VP + c] = packbf(vv.z, vv.w);
        }
        __syncthreads();

        // S = Q^T K : per warp 16x64, TF32 mma, accumulate fresh
        float Sacc[8][4];
        #pragma unroll
        for (int i = 0; i < 8; i++)
            #pragma unroll
            for (int r = 0; r < 4; r++) Sacc[i][r] = 0.f;

        const uint32_t* Qu = (const uint32_t*)qs;
        const uint32_t* Ku = (const uint32_t*)ks;
        #pragma unroll
        for (int k8 = 0; k8 < 8; k8++) {
            uint32_t af[4];
            int r = warp * 16 + g;
            af[0] = Qu[r * QP + k8 * 8 + tg];
            af[1] = Qu[(r + 8) * QP + k8 * 8 + tg];
            af[2] = Qu[r * QP + k8 * 8 + tg + 4];
            af[3] = Qu[(r + 8) * QP + k8 * 8 + tg + 4];
            #pragma unroll
            for (int nt = 0; nt < 8; nt++) {
                uint32_t bf2[2];
                bf2[0] = Ku[(k8 * 8 + tg) * KP + nt * 8 + g];
                bf2[1] = Ku[(k8 * 8 + tg + 4) * KP + nt * 8 + g];
                mma_tf32(Sacc[nt], af, bf2);
            }
        }

        // Online softmax (rows g and g+8; quad reduce over tg lanes)
        float rmax0 = -1e30f, rmax1 = -1e30f;
        #pragma unroll
        for (int nt = 0; nt < 8; nt++) {
            rmax0 = fmaxf(rmax0, fmaxf(Sacc[nt][0], Sacc[nt][1]));
            rmax1 = fmaxf(rmax1, fmaxf(Sacc[nt][2], Sacc[nt][3]));
        }
        rmax0 = fmaxf(rmax0, __shfl_xor_sync(0xffffffffu, rmax0, 1));
        rmax0 = fmaxf(rmax0, __shfl_xor_sync(0xffffffffu, rmax0, 2));
        rmax1 = fmaxf(rmax1, __shfl_xor_sync(0xffffffffu, rmax1, 1));
        rmax1 = fmaxf(rmax1, __shfl_xor_sync(0xffffffffu, rmax1, 2));
        float mn0 = fmaxf(m_i[0], rmax0), mn1 = fmaxf(m_i[1], rmax1);
        float al0 = __expf(m_i[0] - mn0), al1 = __expf(m_i[1] - mn1);

        uint32_t pa[8][2];
        float rs0 = 0.f, rs1 = 0.f;
        #pragma unroll
        for (int nt = 0; nt < 8; nt++) {
            float p0 = __expf(Sacc[nt][0] - mn0);
            float p1 = __expf(Sacc[nt][1] - mn0);
            float p2 = __expf(Sacc[nt][2] - mn1);
            float p3 = __expf(Sacc[nt][3] - mn1);
            rs0 += p0 + p1; rs1 += p2 + p3;
            pa[nt][0] = packbf(p0, p1);
            pa[nt][1] = packbf(p2, p3);
        }
        rs0 += __shfl_xor_sync(0xffffffffu, rs0, 1);
        rs0 += __shfl_xor_sync(0xffffffffu, rs0, 2);
        rs1 += __shfl_xor_sync(0xffffffffu, rs1, 1);
        rs1 += __shfl_xor_sync(0xffffffffu, rs1, 2);
        l_i[0] = l_i[0] * al0 + rs0;
        l_i[1] = l_i[1] * al1 + rs1;
        m_i[0] = mn0; m_i[1] = mn1;
        #pragma unroll
        for (int ct = 0; ct < 8; ct++) {
            Oacc[ct][0] *= al0; Oacc[ct][1] *= al0;
            Oacc[ct][2] *= al1; Oacc[ct][3] *= al1;
        }

        // O += P @ V^T  (bf16 mma, 4 k16-steps over s, 8 c-tiles)
        #pragma unroll
        for (int k16 = 0; k16 < 4; k16++) {
            uint32_t af[4] = { pa[2 * k16][0], pa[2 * k16][1],
                               pa[2 * k16 + 1][0], pa[2 * k16 + 1][1] };
            #pragma unroll
            for (int ct = 0; ct < 8; ct++) {
                uint32_t bf2[2];
                bf2[0] = vsp[(k16 * 8 + tg) * VP + ct * 8 + g];
                bf2[1] = vsp[(k16 * 8 + tg + 4) * VP + ct * 8 + g];
                mma_bf16(Oacc[ct], af, bf2);
            }
        }
    }

    // Normalize + transpose through smem (reuse qs) -> coalesced [c][t] store
    __syncthreads();
    float* osm = qs;
    float inv0 = 1.f / l_i[0], inv1 = 1.f / l_i[1];
    #pragma unroll
    for (int ct = 0; ct < 8; ct++) {
        int c = ct * 8 + 2 * tg;
        int tr = warp * 16 + g;
        osm[(c + 0) * QP + tr]     = Oacc[ct][0] * inv0;
        osm[(c + 1) * QP + tr]     = Oacc[ct][1] * inv0;
        osm[(c + 0) * QP + tr + 8] = Oacc[ct][2] * inv1;
        osm[(c + 1) * QP + tr + 8] = Oacc[ct][3] * inv1;
    }
    __syncthreads();
    size_t obase = (size_t)b * C_ * L_ + (size_t)(hh * CH_) * L_ + t0;
    #pragma unroll
    for (int i = 0; i < 8; i++) {
        int f = tid + 128 * i, c = f >> 4, t4 = (f & 15) * 4;
        float4 v = *(float4*)(osm + c * QP + t4);
        *(float4*)(outa + obase + (size_t)c * L_ + t4) = v;
    }
}

// ---------------------------------------------------------------------------
// Launch
// ---------------------------------------------------------------------------
extern "C" void kernel_launch(void* const* d_in, const int* in_sizes, int n_in,
                              void* d_out, int out_size)
{
    const float* x      = (const float*)d_in[0];
    const float* enc    = (const float*)d_in[1];
    const float* gnsc   = (const float*)d_in[2];
    const float* gnbi   = (const float*)d_in[3];
    const float* w_qkv  = (const float*)d_in[4];
    const float* b_qkv  = (const float*)d_in[5];
    const float* w_ekv  = (const float*)d_in[6];
    const float* b_ekv  = (const float*)d_in[7];
    const float* w_proj = (const float*)d_in[8];
    const float* b_proj = (const float*)d_in[9];
    float* out = (float*)d_out;

    float *h, *qkv, *ekvb, *a;
    cudaGetSymbolAddress((void**)&h,    g_h);
    cudaGetSymbolAddress((void**)&qkv,  g_qkv);
    cudaGetSymbolAddress((void**)&ekvb, g_ekv);
    cudaGetSymbolAddress((void**)&a,    g_a);

    const int GN_SMEM = CPG * L_ * 4;   // 65536
    cudaFuncSetAttribute(gn_kernel, cudaFuncAttributeMaxDynamicSharedMemorySize, GN_SMEM);

    // 1. GroupNorm
    gn_kernel<<<B_ * G_, 256, GN_SMEM>>>(x, gnsc, gnbi, h);

    // 2. qkv = w_qkv @ h + b_qkv   (M=1536, N=1024, K=512, batch 16)
    gemm_tc<false><<<dim3(L_ / 128, 3 * C_ / 128, B_), 256>>>(
        w_qkv, h, b_qkv, nullptr, qkv, 3 * C_, L_, C_);

    // 3. ekv = w_ekv @ enc + b_ekv (M=1024, N=128, K=512, batch 16)
    gemm_tc<false><<<dim3(LE_ / 128, 2 * C_ / 128, B_), 256>>>(
        w_ekv, enc, b_ekv, nullptr, ekvb, 2 * C_, LE_, EC_);

    // 4. attention -> a (B, C, L)
    attn_tc<<<dim3(L_ / 64, B_ * H_), 128>>>(qkv, ekvb, a);

    // 5. out = x + w_proj @ a + b_proj (M=512, N=1024, K=512, batch 16)
    gemm_tc<true><<<dim3(L_ / 128, C_ / 128, B_), 256>>>(
        w_proj, a, b_proj, x, out, C_, L_, C_);
}

// round 3
// speedup vs baseline: 4.2977x; 1.2920x over previous
#include <cuda_runtime.h>
#include <cuda_bf16.h>
#include <math.h>
#include <stddef.h>
#include <stdint.h>

// Problem constants
constexpr int B_  = 16;
constexpr int C_  = 512;
constexpr int L_  = 1024;
constexpr int EC_ = 512;
constexpr int LE_ = 128;
constexpr int H_  = 8;
constexpr int G_  = 32;
constexpr int CH_ = C_ / H_;    // 64
constexpr int CPG = C_ / G_;    // 16

// Scratch (device globals; no dynamic allocation allowed)
__device__ float g_h[B_ * C_ * L_];
__device__ float g_qkv[B_ * 3 * C_ * L_];
__device__ float g_ekv[B_ * 2 * C_ * LE_];
__device__ float g_a[B_ * C_ * L_];

// ---------------------------------------------------------------------------
// Helpers
// ---------------------------------------------------------------------------
__device__ __forceinline__ uint32_t packbf(float lo, float hi) {
    __nv_bfloat162 h = __floats2bfloat162_rn(lo, hi);   // .x = lo halfword
    return *reinterpret_cast<uint32_t*>(&h);
}
__device__ __forceinline__ uint16_t bfbits(float x) {
    __nv_bfloat16 b = __float2bfloat16(x);
    return *reinterpret_cast<uint16_t*>(&b);
}
__device__ __forceinline__ void mma_bf16(float* d, const uint32_t* a, const uint32_t* b) {
    asm volatile("mma.sync.aligned.m16n8k16.row.col.f32.bf16.bf16.f32 "
        "{%0,%1,%2,%3},{%4,%5,%6,%7},{%8,%9},{%0,%1,%2,%3};\n"
        : "+f"(d[0]), "+f"(d[1]), "+f"(d[2]), "+f"(d[3])
        : "r"(a[0]), "r"(a[1]), "r"(a[2]), "r"(a[3]), "r"(b[0]), "r"(b[1]));
}

// ---------------------------------------------------------------------------
// GroupNorm: one block per (b, g). Group cached in smem (single global read).
// ---------------------------------------------------------------------------
__global__ __launch_bounds__(256) void gn_kernel(
    const float* __restrict__ x, const float* __restrict__ sc,
    const float* __restrict__ bi, float* __restrict__ h)
{
    extern __shared__ float buf[];     // 16384 floats (64 KB)
    __shared__ float red[64];
    int b = blockIdx.x >> 5, g = blockIdx.x & 31;
    size_t base = ((size_t)b * C_ + (size_t)g * CPG) * L_;
    const float4* xp = (const float4*)(x + base);
    float4* hp = (float4*)(h + base);

    float s = 0.f, s2 = 0.f;
    for (int i = threadIdx.x; i < CPG * L_ / 4; i += 256) {
        float4 v = xp[i];
        ((float4*)buf)[i] = v;
        s  += v.x + v.y + v.z + v.w;
        s2 += v.x * v.x + v.y * v.y + v.z * v.z + v.w * v.w;
    }
    #pragma unroll
    for (int d = 16; d; d >>= 1) {
        s  += __shfl_xor_sync(0xffffffffu, s, d);
        s2 += __shfl_xor_sync(0xffffffffu, s2, d);
    }
    int warp = threadIdx.x >> 5;
    if ((threadIdx.x & 31) == 0) { red[warp] = s; red[32 + warp] = s2; }
    __syncthreads();
    if (threadIdx.x < 32) {
        s  = (threadIdx.x < 8) ? red[threadIdx.x] : 0.f;
        s2 = (threadIdx.x < 8) ? red[32 + threadIdx.x] : 0.f;
        #pragma unroll
        for (int d = 4; d; d >>= 1) {
            s  += __shfl_xor_sync(0xffffffffu, s, d);
            s2 += __shfl_xor_sync(0xffffffffu, s2, d);
        }
        if (threadIdx.x == 0) { red[0] = s; red[1] = s2; }
    }
    __syncthreads();
    const float inv_n = 1.f / (float)(CPG * L_);
    float mean = red[0] * inv_n;
    float var  = red[1] * inv_n - mean * mean;
    float rstd = rsqrtf(var + 1e-5f);
    for (int i = threadIdx.x; i < CPG * L_ / 4; i += 256) {
        int c = g * CPG + (i >> 8);
        float a  = sc[c] * rstd;
        float bb = bi[c] - mean * a;
        float4 v = ((float4*)buf)[i];
        v.x = v.x * a + bb; v.y = v.y * a + bb;
        v.z = v.z * a + bb; v.w = v.w * a + bb;
        hp[i] = v;
    }
}

// ---------------------------------------------------------------------------
// bf16 tensor-core batched GEMM: C[z] = A(MxK, shared) * B[z](KxN) + bias
// (+ optional fp32 residual). 128x128 tile, k-chunk 32 (2 x k16), 256 threads
// = 8 warps in 4(m) x 2(n); warp tile 32x64.
// As [128 rows][16 kpairs] u32, row stride 20 (frag banks 20g+tg distinct).
// Bs [16 kpairs][128 n]   u32, row stride 136 (frag banks 8tg+g distinct).
// ---------------------------------------------------------------------------
constexpr int GAP = 20;
constexpr int GBP = 136;

template<bool RES>
__global__ __launch_bounds__(256) void gemm_bf(
    const float* __restrict__ A, const float* __restrict__ Bm,
    const float* __restrict__ bias, const float* __restrict__ res,
    float* __restrict__ Cm, int M, int N, int K)
{
    __shared__ __align__(16) uint32_t As[128 * GAP];
    __shared__ __align__(16) uint32_t Bs[16 * GBP];
    int tid = threadIdx.x, lane = tid & 31, warp = tid >> 5;
    int g = lane >> 2, tg = lane & 3;
    int wm = warp >> 1, wn = warp & 1;
    int m0 = blockIdx.y * 128, n0 = blockIdx.x * 128;
    const float* Bp = Bm + (size_t)blockIdx.z * K * N;

    float acc[2][8][4];
    #pragma unroll
    for (int i = 0; i < 2; i++)
        #pragma unroll
        for (int j = 0; j < 8; j++)
            #pragma unroll
            for (int r = 0; r < 4; r++) acc[i][j][r] = 0.f;

    for (int k0 = 0; k0 < K; k0 += 32) {
        __syncthreads();
        // A tile 128x32 -> As[row][kpair]
        #pragma unroll
        for (int i = 0; i < 4; i++) {
            int f = tid + 256 * i, row = f >> 3, k4 = (f & 7) * 4;
            float4 v = *(const float4*)(A + (size_t)(m0 + row) * K + k0 + k4);
            uint2 w = make_uint2(packbf(v.x, v.y), packbf(v.z, v.w));
            *(uint2*)&As[row * GAP + (k4 >> 1)] = w;
        }
        // B tile 32x128 -> Bs[kpair][n] (pairs across adjacent k-rows)
        #pragma unroll
        for (int i = 0; i < 2; i++) {
            int f = tid + 256 * i, kpr = f >> 5, n4 = (f & 31) * 4;
            const float* rp = Bp + (size_t)(k0 + 2 * kpr) * N + n0 + n4;
            float4 v0 = *(const float4*)rp;
            float4 v1 = *(const float4*)(rp + N);
            uint4 w = make_uint4(packbf(v0.x, v1.x), packbf(v0.y, v1.y),
                                 packbf(v0.z, v1.z), packbf(v0.w, v1.w));
            *(uint4*)&Bs[kpr * GBP + n4] = w;
        }
        __syncthreads();

        #pragma unroll
        for (int k16 = 0; k16 < 2; k16++) {
            uint32_t af[2][4], bf[8][2];
            #pragma unroll
            for (int mt = 0; mt < 2; mt++) {
                int r = wm * 32 + mt * 16 + g;
                af[mt][0] = As[r * GAP + k16 * 8 + tg];
                af[mt][1] = As[(r + 8) * GAP + k16 * 8 + tg];
                af[mt][2] = As[r * GAP + k16 * 8 + tg + 4];
                af[mt][3] = As[(r + 8) * GAP + k16 * 8 + tg + 4];
            }
            #pragma unroll
            for (int nt = 0; nt < 8; nt++) {
                int c = wn * 64 + nt * 8 + g;
                bf[nt][0] = Bs[(k16 * 8 + tg) * GBP + c];
                bf[nt][1] = Bs[(k16 * 8 + tg + 4) * GBP + c];
            }
            #pragma unroll
            for (int mt = 0; mt < 2; mt++)
                #pragma unroll
                for (int nt = 0; nt < 8; nt++)
                    mma_bf16(acc[mt][nt], af[mt], bf[nt]);
        }
    }

    // Epilogue (fp32 bias / residual)
    float* Cp = Cm + (size_t)blockIdx.z * M * N;
    const float* Rp = RES ? (res + (size_t)blockIdx.z * M * N) : nullptr;
    #pragma unroll
    for (int mt = 0; mt < 2; mt++) {
        int r0 = m0 + wm * 32 + mt * 16 + g;
        float bv0 = bias[r0], bv1 = bias[r0 + 8];
        #pragma unroll
        for (int nt = 0; nt < 8; nt++) {
            int c = n0 + wn * 64 + nt * 8 + 2 * tg;
            float2 v0 = make_float2(acc[mt][nt][0] + bv0, acc[mt][nt][1] + bv0);
            float2 v1 = make_float2(acc[mt][nt][2] + bv1, acc[mt][nt][3] + bv1);
            size_t o0 = (size_t)r0 * N + c;
            size_t o1 = (size_t)(r0 + 8) * N + c;
            if (RES) {
                float2 r0v = *(const float2*)(Rp + o0);
                float2 r1v = *(const float2*)(Rp + o1);
                v0.x += r0v.x; v0.y += r0v.y;
                v1.x += r1v.x; v1.y += r1v.y;
            }
            *(float2*)(Cp + o0) = v0;
            *(float2*)(Cp + o1) = v1;
        }
    }
}

// ---------------------------------------------------------------------------
// Flash attention, all-bf16 m16n8k16.
// Grid (L/128, B*H), 256 threads = 8 warps; warp w owns q-rows w*16..w*16+15.
// qs [t<128][kpair<32] u32 stride 36 (frag banks 4g+tg distinct)
// ku [kpair<32][s<64]  u32 stride 72 (frag banks 8tg+g distinct)
// vu [spair<32][c<64]  u32 stride 72
// ---------------------------------------------------------------------------
constexpr int QPu = 36;
constexpr int KPu = 72;
constexpr int VPu = 72;
constexpr int OT  = 132;   // osm [c][t] float stride (banks 8tg+g distinct)

__global__ __launch_bounds__(256) void attn_tc(
    const float* __restrict__ qkv, const float* __restrict__ ekv,
    float* __restrict__ outa)
{
    __shared__ __align__(16) uint32_t sm[9216];   // 36 KB
    uint32_t* qs = sm;                 // 128*36 = 4608
    uint32_t* ku = sm + 4608;          // 32*72  = 2304
    uint32_t* vu = sm + 6912;          // 32*72  = 2304

    int tid = threadIdx.x, lane = tid & 31, warp = tid >> 5;
    int g = lane >> 2, tg = lane & 3;
    int t0 = blockIdx.x * 128;
    int bh = blockIdx.y, b = bh >> 3, hh = bh & 7;

    const float* qp  = qkv + ((size_t)b * (3 * C_) + (size_t)hh * (3 * CH_)) * L_;
    const float* kqp = qp + (size_t)CH_ * L_;
    const float* vqp = qp + (size_t)2 * CH_ * L_;
    const float* ekp = ekv + ((size_t)b * (2 * C_) + (size_t)hh * (2 * CH_)) * LE_;
    const float* evp = ekp + (size_t)CH_ * LE_;

    // Load Q tile 64c x 128t -> qs[t][kpair] bf16 halves, scaled 1/8
    uint16_t* qh = (uint16_t*)qs;
    #pragma unroll
    for (int i = 0; i < 8; i++) {
        int f = tid + 256 * i, c = f >> 5, t4 = (f & 31) * 4;
        float4 v = *(const float4*)(qp + (size_t)c * L_ + t0 + t4);
        int base = (c >> 1), half = c & 1;
        qh[((t4 + 0) * QPu + base) * 2 + half] = bfbits(v.x * 0.125f);
        qh[((t4 + 1) * QPu + base) * 2 + half] = bfbits(v.y * 0.125f);
        qh[((t4 + 2) * QPu + base) * 2 + half] = bfbits(v.z * 0.125f);
        qh[((t4 + 3) * QPu + base) * 2 + half] = bfbits(v.w * 0.125f);
    }

    float m_i[2] = {-1e30f, -1e30f}, l_i[2] = {0.f, 0.f};
    float Oacc[8][4];
    #pragma unroll
    for (int i = 0; i < 8; i++)
        #pragma unroll
        for (int r = 0; r < 4; r++) Oacc[i][r] = 0.f;

    uint16_t* kh = (uint16_t*)ku;
    for (int ci = 0; ci < (LE_ + L_) / 64; ci++) {
        int s0 = ci * 64;
        const float* kp; const float* vp; int ld, off;
        if (s0 < LE_) { kp = ekp; vp = evp; ld = LE_; off = s0; }
        else          { kp = kqp; vp = vqp; ld = L_;  off = s0 - LE_; }

        __syncthreads();   // previous chunk fully consumed
        #pragma unroll
        for (int i = 0; i < 4; i++) {
            int f = tid + 256 * i, c = f >> 4, s4 = (f & 15) * 4;
            float4 kv = *(const float4*)(kp + (size_t)c * ld + off + s4);
            int base = (c >> 1) * KPu, half = c & 1;
            kh[(base + s4 + 0) * 2 + half] = bfbits(kv.x);
            kh[(base + s4 + 1) * 2 + half] = bfbits(kv.y);
            kh[(base + s4 + 2) * 2 + half] = bfbits(kv.z);
            kh[(base + s4 + 3) * 2 + half] = bfbits(kv.w);
            float4 vv = *(const float4*)(vp + (size_t)c * ld + off + s4);
            vu[((s4 >> 1) + 0) * VPu + c] = packbf(vv.x, vv.y);
            vu[((s4 >> 1) + 1) * VPu + c] = packbf(vv.z, vv.w);
        }
        __syncthreads();

        // S = Q^T K : per warp 16x64, 4 k16-steps over channels
        float Sacc[8][4];
        #pragma unroll
        for (int i = 0; i < 8; i++)
            #pragma unroll
            for (int r = 0; r < 4; r++) Sacc[i][r] = 0.f;

        int r = warp * 16 + g;
        #pragma unroll
        for (int k16 = 0; k16 < 4; k16++) {
            uint32_t af[4];
            af[0] = qs[r * QPu + k16 * 8 + tg];
            af[1] = qs[(r + 8) * QPu + k16 * 8 + tg];
            af[2] = qs[r * QPu + k16 * 8 + tg + 4];
            af[3] = qs[(r + 8) * QPu + k16 * 8 + tg + 4];
            #pragma unroll
            for (int nt = 0; nt < 8; nt++) {
                uint32_t bfr[2];
                bfr[0] = ku[(k16 * 8 + tg) * KPu + nt * 8 + g];
                bfr[1] = ku[(k16 * 8 + tg + 4) * KPu + nt * 8 + g];
                mma_bf16(Sacc[nt], af, bfr);
            }
        }

        // Online softmax (rows g and g+8; quad reduce over tg lanes)
        float rmax0 = -1e30f, rmax1 = -1e30f;
        #pragma unroll
        for (int nt = 0; nt < 8; nt++) {
            rmax0 = fmaxf(rmax0, fmaxf(Sacc[nt][0], Sacc[nt][1]));
            rmax1 = fmaxf(rmax1, fmaxf(Sacc[nt][2], Sacc[nt][3]));
        }
        rmax0 = fmaxf(rmax0, __shfl_xor_sync(0xffffffffu, rmax0, 1));
        rmax0 = fmaxf(rmax0, __shfl_xor_sync(0xffffffffu, rmax0, 2));
        rmax1 = fmaxf(rmax1, __shfl_xor_sync(0xffffffffu, rmax1, 1));
        rmax1 = fmaxf(rmax1, __shfl_xor_sync(0xffffffffu, rmax1, 2));
        float mn0 = fmaxf(m_i[0], rmax0), mn1 = fmaxf(m_i[1], rmax1);
        float al0 = __expf(m_i[0] - mn0), al1 = __expf(m_i[1] - mn1);

        uint32_t pa[8][2];
        float rs0 = 0.f, rs1 = 0.f;
        #pragma unroll
        for (int nt = 0; nt < 8; nt++) {
            float p0 = __expf(Sacc[nt][0] - mn0);
            float p1 = __expf(Sacc[nt][1] - mn0);
            float p2 = __expf(Sacc[nt][2] - mn1);
            float p3 = __expf(Sacc[nt][3] - mn1);
            rs0 += p0 + p1; rs1 += p2 + p3;
            pa[nt][0] = packbf(p0, p1);
            pa[nt][1] = packbf(p2, p3);
        }
        rs0 += __shfl_xor_sync(0xffffffffu, rs0, 1);
        rs0 += __shfl_xor_sync(0xffffffffu, rs0, 2);
        rs1 += __shfl_xor_sync(0xffffffffu, rs1, 1);
        rs1 += __shfl_xor_sync(0xffffffffu, rs1, 2);
        l_i[0] = l_i[0] * al0 + rs0;
        l_i[1] = l_i[1] * al1 + rs1;
        m_i[0] = mn0; m_i[1] = mn1;
        #pragma unroll
        for (int ct = 0; ct < 8; ct++) {
            Oacc[ct][0] *= al0; Oacc[ct][1] *= al0;
            Oacc[ct][2] *= al1; Oacc[ct][3] *= al1;
        }

        // O += P @ V^T  (4 k16-steps over s, 8 c-tiles)
        #pragma unroll
        for (int k16 = 0; k16 < 4; k16++) {
            uint32_t af[4] = { pa[2 * k16][0], pa[2 * k16][1],
                               pa[2 * k16 + 1][0], pa[2 * k16 + 1][1] };
            #pragma unroll
            for (int ct = 0; ct < 8; ct++) {
                uint32_t bfr[2];
                bfr[0] = vu[(k16 * 8 + tg) * VPu + ct * 8 + g];
                bfr[1] = vu[(k16 * 8 + tg + 4) * VPu + ct * 8 + g];
                mma_bf16(Oacc[ct], af, bfr);
            }
        }
    }

    // Normalize + transpose through smem (overlay) -> coalesced [c][t] store
    __syncthreads();
    float* osm = (float*)sm;     // 64 x OT floats = 8448 <= 9216
    float inv0 = 1.f / l_i[0], inv1 = 1.f / l_i[1];
    int tr = warp * 16 + g;
    #pragma unroll
    for (int ct = 0; ct < 8; ct++) {
        int c = ct * 8 + 2 * tg;
        osm[(c + 0) * OT + tr]     = Oacc[ct][0] * inv0;
        osm[(c + 1) * OT + tr]     = Oacc[ct][1] * inv0;
        osm[(c + 0) * OT + tr + 8] = Oacc[ct][2] * inv1;
        osm[(c + 1) * OT + tr + 8] = Oacc[ct][3] * inv1;
    }
    __syncthreads();
    size_t obase = (size_t)b * C_ * L_ + (size_t)(hh * CH_) * L_ + t0;
    #pragma unroll
    for (int i = 0; i < 8; i++) {
        int f = tid + 256 * i, c = f >> 5, t4 = (f & 31) * 4;
        float4 v = *(float4*)(osm + c * OT + t4);
        *(float4*)(outa + obase + (size_t)c * L_ + t4) = v;
    }
}

// ---------------------------------------------------------------------------
// Launch
// ---------------------------------------------------------------------------
extern "C" void kernel_launch(void* const* d_in, const int* in_sizes, int n_in,
                              void* d_out, int out_size)
{
    const float* x      = (const float*)d_in[0];
    const float* enc    = (const float*)d_in[1];
    const float* gnsc   = (const float*)d_in[2];
    const float* gnbi   = (const float*)d_in[3];
    const float* w_qkv  = (const float*)d_in[4];
    const float* b_qkv  = (const float*)d_in[5];
    const float* w_ekv  = (const float*)d_in[6];
    const float* b_ekv  = (const float*)d_in[7];
    const float* w_proj = (const float*)d_in[8];
    const float* b_proj = (const float*)d_in[9];
    float* out = (float*)d_out;

    float *h, *qkv, *ekvb, *a;
    cudaGetSymbolAddress((void**)&h,    g_h);
    cudaGetSymbolAddress((void**)&qkv,  g_qkv);
    cudaGetSymbolAddress((void**)&ekvb, g_ekv);
    cudaGetSymbolAddress((void**)&a,    g_a);

    const int GN_SMEM = CPG * L_ * 4;   // 65536
    cudaFuncSetAttribute(gn_kernel, cudaFuncAttributeMaxDynamicSharedMemorySize, GN_SMEM);

    // 1. GroupNorm
    gn_kernel<<<B_ * G_, 256, GN_SMEM>>>(x, gnsc, gnbi, h);

    // 2. qkv = w_qkv @ h + b_qkv   (M=1536, N=1024, K=512, batch 16)
    gemm_bf<false><<<dim3(L_ / 128, 3 * C_ / 128, B_), 256>>>(
        w_qkv, h, b_qkv, nullptr, qkv, 3 * C_, L_, C_);

    // 3. ekv = w_ekv @ enc + b_ekv (M=1024, N=128, K=512, batch 16)
    gemm_bf<false><<<dim3(LE_ / 128, 2 * C_ / 128, B_), 256>>>(
        w_ekv, enc, b_ekv, nullptr, ekvb, 2 * C_, LE_, EC_);

    // 4. attention -> a (B, C, L)
    attn_tc<<<dim3(L_ / 128, B_ * H_), 256>>>(qkv, ekvb, a);

    // 5. out = x + w_proj @ a + b_proj (M=512, N=1024, K=512, batch 16)
    gemm_bf<true><<<dim3(L_ / 128, C_ / 128, B_), 256>>>(
        w_proj, a, b_proj, x, out, C_, L_, C_);
}

// round 5
// speedup vs baseline: 6.3029x; 1.4666x over previous
#include <cuda_runtime.h>
#include <cuda_bf16.h>
#include <math.h>
#include <stddef.h>
#include <stdint.h>

// Problem constants
constexpr int B_  = 16;
constexpr int C_  = 512;
constexpr int L_  = 1024;
constexpr int EC_ = 512;
constexpr int LE_ = 128;
constexpr int H_  = 8;
constexpr int G_  = 32;
constexpr int CH_ = C_ / H_;    // 64
constexpr int CPG = C_ / G_;    // 16

// Scratch (device globals; no dynamic allocation allowed) — all bf16
__device__ __nv_bfloat16 gb_h[B_ * C_ * L_];
__device__ __nv_bfloat16 gb_qkv[B_ * 3 * C_ * L_];
__device__ __nv_bfloat16 gb_ekv[B_ * 2 * C_ * LE_];
__device__ __nv_bfloat16 gb_a[B_ * C_ * L_];
__device__ __nv_bfloat16 gb_wqkv[3 * C_ * C_];
__device__ __nv_bfloat16 gb_wekv[2 * C_ * EC_];
__device__ __nv_bfloat16 gb_wproj[C_ * C_];
__device__ __nv_bfloat16 gb_enc[B_ * EC_ * LE_];

// ---------------------------------------------------------------------------
// Helpers
// ---------------------------------------------------------------------------
__device__ __forceinline__ uint32_t packbf(float lo, float hi) {
    __nv_bfloat162 h = __floats2bfloat162_rn(lo, hi);
    return *reinterpret_cast<uint32_t*>(&h);
}
__device__ __forceinline__ void mma_bf16(float* d, const uint32_t* a, const uint32_t* b) {
    asm volatile("mma.sync.aligned.m16n8k16.row.col.f32.bf16.bf16.f32 "
        "{%0,%1,%2,%3},{%4,%5,%6,%7},{%8,%9},{%0,%1,%2,%3};\n"
        : "+f"(d[0]), "+f"(d[1]), "+f"(d[2]), "+f"(d[3])
        : "r"(a[0]), "r"(a[1]), "r"(a[2]), "r"(a[3]), "r"(b[0]), "r"(b[1]));
}
__device__ __forceinline__ uint32_t saddr(const void* p) {
    return (uint32_t)__cvta_generic_to_shared(p);
}
__device__ __forceinline__ void cp16(uint32_t dst, const void* src) {
    asm volatile("cp.async.cg.shared.global [%0], [%1], 16;\n" :: "r"(dst), "l"(src));
}
__device__ __forceinline__ void cp16ca(uint32_t dst, const void* src) {
    asm volatile("cp.async.ca.shared.global [%0], [%1], 16;\n" :: "r"(dst), "l"(src));
}
__device__ __forceinline__ void cp_commit() { asm volatile("cp.async.commit_group;\n"); }
template<int N> __device__ __forceinline__ void cp_wait() {
    asm volatile("cp.async.wait_group %0;\n" :: "n"(N));
}
__device__ __forceinline__ void ldsm4(uint32_t* r, uint32_t a) {
    asm volatile("ldmatrix.sync.aligned.m8n8.x4.shared.b16 {%0,%1,%2,%3}, [%4];\n"
        : "=r"(r[0]), "=r"(r[1]), "=r"(r[2]), "=r"(r[3]) : "r"(a));
}
__device__ __forceinline__ void ldsm4t(uint32_t* r, uint32_t a) {
    asm volatile("ldmatrix.sync.aligned.m8n8.x4.trans.shared.b16 {%0,%1,%2,%3}, [%4];\n"
        : "=r"(r[0]), "=r"(r[1]), "=r"(r[2]), "=r"(r[3]) : "r"(a));
}

// ---------------------------------------------------------------------------
// fp32 -> bf16 elementwise conversion (weights / encoder_out)
// ---------------------------------------------------------------------------
__global__ __launch_bounds__(256) void cvt_kernel(
    const float4* __restrict__ src, uint2* __restrict__ dst, int n4)
{
    int i = blockIdx.x * 256 + threadIdx.x;
    if (i < n4) {
        float4 v = src[i];
        dst[i] = make_uint2(packbf(v.x, v.y), packbf(v.z, v.w));
    }
}

// ---------------------------------------------------------------------------
// GroupNorm -> bf16 output. One block per (b, g), group cached in smem.
// ---------------------------------------------------------------------------
__global__ __launch_bounds__(256) void gn_kernel(
    const float* __restrict__ x, const float* __restrict__ sc,
    const float* __restrict__ bi, __nv_bfloat16* __restrict__ h)
{
    extern __shared__ float buf[];     // 16384 floats (64 KB)
    __shared__ float red[64];
    int b = blockIdx.x >> 5, g = blockIdx.x & 31;
    size_t base = ((size_t)b * C_ + (size_t)g * CPG) * L_;
    const float4* xp = (const float4*)(x + base);
    uint2* hp = (uint2*)(h + base);

    float s = 0.f, s2 = 0.f;
    for (int i = threadIdx.x; i < CPG * L_ / 4; i += 256) {
        float4 v = xp[i];
        ((float4*)buf)[i] = v;
        s  += v.x + v.y + v.z + v.w;
        s2 += v.x * v.x + v.y * v.y + v.z * v.z + v.w * v.w;
    }
    #pragma unroll
    for (int d = 16; d; d >>= 1) {
        s  += __shfl_xor_sync(0xffffffffu, s, d);
        s2 += __shfl_xor_sync(0xffffffffu, s2, d);
    }
    int warp = threadIdx.x >> 5;
    if ((threadIdx.x & 31) == 0) { red[warp] = s; red[32 + warp] = s2; }
    __syncthreads();
    if (threadIdx.x < 32) {
        s  = (threadIdx.x < 8) ? red[threadIdx.x] : 0.f;
        s2 = (threadIdx.x < 8) ? red[32 + threadIdx.x] : 0.f;
        #pragma unroll
        for (int d = 4; d; d >>= 1) {
            s  += __shfl_xor_sync(0xffffffffu, s, d);
            s2 += __shfl_xor_sync(0xffffffffu, s2, d);
        }
        if (threadIdx.x == 0) { red[0] = s; red[1] = s2; }
    }
    __syncthreads();
    const float inv_n = 1.f / (float)(CPG * L_);
    float mean = red[0] * inv_n;
    float var  = red[1] * inv_n - mean * mean;
    float rstd = rsqrtf(var + 1e-5f);
    for (int i = threadIdx.x; i < CPG * L_ / 4; i += 256) {
        int c = g * CPG + (i >> 8);
        float a  = sc[c] * rstd;
        float bb = bi[c] - mean * a;
        float4 v = ((float4*)buf)[i];
        hp[i] = make_uint2(packbf(v.x * a + bb, v.y * a + bb),
                           packbf(v.z * a + bb, v.w * a + bb));
    }
}

// ---------------------------------------------------------------------------
// bf16 GEMM with cp.async double buffering + ldmatrix fragments.
// C[z] = A(MxK bf16, shared) * B[z](KxN bf16) + bias (+ fp32 residual).
// 128x128 tile, k-chunk 32, 256 threads = 8 warps (4m x 2n), warp 32x64.
// ---------------------------------------------------------------------------
constexpr int ASTR = 40;
constexpr int BSTR = 136;

template<bool RES, bool OUTBF>
__global__ __launch_bounds__(256) void gemm_cp(
    const __nv_bfloat16* __restrict__ A, const __nv_bfloat16* __restrict__ Bm,
    const float* __restrict__ bias, const float* __restrict__ res,
    void* __restrict__ Cm, int M, int N, int K)
{
    __shared__ __align__(16) uint16_t As[2][128 * ASTR];
    __shared__ __align__(16) uint16_t Bs[2][32 * BSTR];
    int tid = threadIdx.x, lane = tid & 31, warp = tid >> 5;
    int g = lane >> 2, tg = lane & 3;
    int r8 = lane & 7, grp = lane >> 3;
    int wm = warp >> 1, wn = warp & 1;
    int m0 = blockIdx.y * 128, n0 = blockIdx.x * 128;
    const __nv_bfloat16* Bp = Bm + (size_t)blockIdx.z * K * N;

    float acc[2][8][4];
    #pragma unroll
    for (int i = 0; i < 2; i++)
        #pragma unroll
        for (int j = 0; j < 8; j++)
            #pragma unroll
            for (int r = 0; r < 4; r++) acc[i][j][r] = 0.f;

    auto issue = [&](int st, int k0) {
        #pragma unroll
        for (int i = 0; i < 2; i++) {   // A: 128 rows x 4 segs of 16B
            int id = tid + 256 * i, row = id >> 2, seg = id & 3;
            cp16ca(saddr(&As[st][row * ASTR + seg * 8]),
                   A + (size_t)(m0 + row) * K + k0 + seg * 8);
        }
        #pragma unroll
        for (int i = 0; i < 2; i++) {   // B: 32 rows x 16 segs of 16B
            int id = tid + 256 * i, row = id >> 4, seg = id & 15;
            cp16(saddr(&Bs[st][row * BSTR + seg * 8]),
                 Bp + (size_t)(k0 + row) * N + n0 + seg * 8);
        }
    };

    issue(0, 0);
    cp_commit();

    int nk = K / 32;
    for (int kt = 0; kt < nk; kt++) {
        if (kt + 1 < nk) issue((kt + 1) & 1, (kt + 1) * 32);
        cp_commit();
        cp_wait<1>();
        __syncthreads();
        const uint16_t* as = As[kt & 1];
        const uint16_t* bs = Bs[kt & 1];
        #pragma unroll
        for (int k16 = 0; k16 < 2; k16++) {
            uint32_t af[2][4], bfr[4][4];
            #pragma unroll
            for (int mt = 0; mt < 2; mt++) {
                int row = wm * 32 + mt * 16 + (grp & 1) * 8 + r8;
                int col = k16 * 16 + (grp >> 1) * 8;
                ldsm4(af[mt], saddr(as + row * ASTR + col));
            }
            #pragma unroll
            for (int p = 0; p < 4; p++) {
                int row = k16 * 16 + (grp & 1) * 8 + r8;
                int col = wn * 64 + p * 16 + (grp >> 1) * 8;
                ldsm4t(bfr[p], saddr(bs + row * BSTR + col));
            }
            #pragma unroll
            for (int mt = 0; mt < 2; mt++)
                #pragma unroll
                for (int p = 0; p < 4; p++) {
                    mma_bf16(acc[mt][2 * p],     af[mt], &bfr[p][0]);
                    mma_bf16(acc[mt][2 * p + 1], af[mt], &bfr[p][2]);
                }
        }
        __syncthreads();
    }

    // Epilogue. acc[mt][nt]: n base = wn*64 + (nt>>1)*16 + (nt&1)*8.
    #pragma unroll
    for (int mt = 0; mt < 2; mt++) {
        int r0 = m0 + wm * 32 + mt * 16 + g;
        float bv0 = bias[r0], bv1 = bias[r0 + 8];
        #pragma unroll
        for (int nt = 0; nt < 8; nt++) {
            int c = n0 + wn * 64 + (nt >> 1) * 16 + (nt & 1) * 8 + 2 * tg;
            size_t o0 = (size_t)(r0) * N + c + (size_t)blockIdx.z * M * N;
            size_t o1 = (size_t)(r0 + 8) * N + c + (size_t)blockIdx.z * M * N;
            float v0 = acc[mt][nt][0] + bv0, v1 = acc[mt][nt][1] + bv0;
            float v2 = acc[mt][nt][2] + bv1, v3 = acc[mt][nt][3] + bv1;
            if (OUTBF) {
                __nv_bfloat16* Cb = (__nv_bfloat16*)Cm;
                *(uint32_t*)(Cb + o0) = packbf(v0, v1);
                *(uint32_t*)(Cb + o1) = packbf(v2, v3);
            } else {
                float* Cf = (float*)Cm;
                if (RES) {
                    float2 ra = *(const float2*)(res + o0);
                    float2 rb = *(const float2*)(res + o1);
                    v0 += ra.x; v1 += ra.y; v2 += rb.x; v3 += rb.y;
                }
                *(float2*)(Cf + o0) = make_float2(v0, v1);
                *(float2*)(Cf + o1) = make_float2(v2, v3);
            }
        }
    }
}

// ---------------------------------------------------------------------------
// Flash attention: bf16 in/out, ldmatrix fragments, cp.async double buffer.
// Grid (L/128, B*H), 128 threads = 4 warps; warp owns 32 q-rows (2 m-tiles).
// ---------------------------------------------------------------------------
constexpr int QSTR = 136;
constexpr int KSTR = 72;
constexpr int KSTG = 64 * KSTR;        // u16 per stage
constexpr int ATTN_SMEM = (64 * QSTR + 4 * KSTG) * 2;   // 54272 bytes

__global__ __launch_bounds__(128) void attn_tc(
    const __nv_bfloat16* __restrict__ qkv, const __nv_bfloat16* __restrict__ ekv,
    __nv_bfloat16* __restrict__ outa)
{
    extern __shared__ __align__(16) uint16_t dsm[];
    uint16_t* qs  = dsm;                        // 64*136
    uint16_t* ksm = dsm + 64 * QSTR;            // 2 stages
    uint16_t* vsm = dsm + 64 * QSTR + 2 * KSTG; // 2 stages

    int tid = threadIdx.x, lane = tid & 31, warp = tid >> 5;
    int g = lane >> 2, tg = lane & 3;
    int r8 = lane & 7, grp = lane >> 3;
    int t0 = blockIdx.x * 128;
    int bh = blockIdx.y, b = bh >> 3, hh = bh & 7;

    const __nv_bfloat16* qp  = qkv + ((size_t)b * (3 * C_) + (size_t)hh * (3 * CH_)) * L_;
    const __nv_bfloat16* kqp = qp + (size_t)CH_ * L_;
    const __nv_bfloat16* vqp = qp + (size_t)2 * CH_ * L_;
    const __nv_bfloat16* ekp = ekv + ((size_t)b * (2 * C_) + (size_t)hh * (2 * CH_)) * LE_;
    const __nv_bfloat16* evp = ekp + (size_t)CH_ * LE_;

    auto issueKV = [&](int st, int ci) {
        int s0 = ci * 64;
        const __nv_bfloat16 *kp, *vp; int ld, off;
        if (s0 < LE_) { kp = ekp; vp = evp; ld = LE_; off = s0; }
        else          { kp = kqp; vp = vqp; ld = L_;  off = s0 - LE_; }
        #pragma unroll
        for (int i = 0; i < 4; i++) {   // 64 rows x 8 segs of 16B
            int id = tid + 128 * i, row = id >> 3, seg = id & 7;
            cp16(saddr(ksm + st * KSTG + row * KSTR + seg * 8),
                 kp + (size_t)row * ld + off + seg * 8);
            cp16(saddr(vsm + st * KSTG + row * KSTR + seg * 8),
                 vp + (size_t)row * ld + off + seg * 8);
        }
    };

    // Prologue: Q tile + KV chunk 0
    #pragma unroll
    for (int i = 0; i < 8; i++) {       // 64 rows x 16 segs of 16B
        int id = tid + 128 * i, row = id >> 4, seg = id & 15;
        cp16(saddr(qs + row * QSTR + seg * 8),
             qp + (size_t)row * L_ + t0 + seg * 8);
    }
    issueKV(0, 0);
    cp_commit();

    float m_i[4] = {-1e30f, -1e30f, -1e30f, -1e30f};
    float l_i[4] = {0.f, 0.f, 0.f, 0.f};
    float Oacc[2][8][4];
    #pragma unroll
    for (int mt = 0; mt < 2; mt++)
        #pragma unroll
        for (int i = 0; i < 8; i++)
            #pragma unroll
            for (int r = 0; r < 4; r++) Oacc[mt][i][r] = 0.f;

    uint32_t qf[2][4][4];
    constexpr int NCH = (LE_ + L_) / 64;   // 18
    constexpr float SC = 0.125f;           // 1/sqrt(ch) = 1/8

    for (int kt = 0; kt < NCH; kt++) {
        if (kt + 1 < NCH) issueKV((kt + 1) & 1, kt + 1);
        cp_commit();
        cp_wait<1>();
        __syncthreads();

        if (kt == 0) {
            // Hoist Q fragments (A of S-mma)
            #pragma unroll
            for (int mt = 0; mt < 2; mt++)
                #pragma unroll
                for (int k16 = 0; k16 < 4; k16++) {
                    int row = k16 * 16 + (grp >> 1) * 8 + r8;
                    int col = warp * 32 + mt * 16 + (grp & 1) * 8;
                    ldsm4t(qf[mt][k16], saddr(qs + row * QSTR + col));
                }
        }

        const uint16_t* ks = ksm + (kt & 1) * KSTG;
        const uint16_t* vs = vsm + (kt & 1) * KSTG;

        // S = Q^T K (softmax temperature applied on fp32 S below)
        float Sacc[2][8][4];
        #pragma unroll
        for (int mt = 0; mt < 2; mt++)
            #pragma unroll
            for (int i = 0; i < 8; i++)
                #pragma unroll
                for (int r = 0; r < 4; r++) Sacc[mt][i][r] = 0.f;

        #pragma unroll
        for (int k16 = 0; k16 < 4; k16++) {
            uint32_t kb[4][4];
            #pragma unroll
            for (int p = 0; p < 4; p++) {
                int row = k16 * 16 + (grp & 1) * 8 + r8;
                int col = p * 16 + (grp >> 1) * 8;
                ldsm4t(kb[p], saddr(ks + row * KSTR + col));
            }
            #pragma unroll
            for (int mt = 0; mt < 2; mt++)
                #pragma unroll
                for (int p = 0; p < 4; p++) {
                    mma_bf16(Sacc[mt][2 * p],     qf[mt][k16], &kb[p][0]);
                    mma_bf16(Sacc[mt][2 * p + 1], qf[mt][k16], &kb[p][2]);
                }
        }

        // Online softmax. Row stats: [mt*2] = row g, [mt*2+1] = row g+8.
        uint32_t pa[2][8][2];
        #pragma unroll
        for (int mt = 0; mt < 2; mt++) {
            float rmax0 = -1e30f, rmax1 = -1e30f;
            #pragma unroll
            for (int nt = 0; nt < 8; nt++) {
                rmax0 = fmaxf(rmax0, fmaxf(Sacc[mt][nt][0], Sacc[mt][nt][1]));
                rmax1 = fmaxf(rmax1, fmaxf(Sacc[mt][nt][2], Sacc[mt][nt][3]));
            }
            rmax0 = fmaxf(rmax0, __shfl_xor_sync(0xffffffffu, rmax0, 1));
            rmax0 = fmaxf(rmax0, __shfl_xor_sync(0xffffffffu, rmax0, 2));
            rmax1 = fmaxf(rmax1, __shfl_xor_sync(0xffffffffu, rmax1, 1));
            rmax1 = fmaxf(rmax1, __shfl_xor_sync(0xffffffffu, rmax1, 2));
            rmax0 *= SC; rmax1 *= SC;
            float mn0 = fmaxf(m_i[mt * 2], rmax0);
            float mn1 = fmaxf(m_i[mt * 2 + 1], rmax1);
            float al0 = __expf(m_i[mt * 2] - mn0);
            float al1 = __expf(m_i[mt * 2 + 1] - mn1);
            float rs0 = 0.f, rs1 = 0.f;
            #pragma unroll
            for (int nt = 0; nt < 8; nt++) {
                float p0 = __expf(Sacc[mt][nt][0] * SC - mn0);
                float p1 = __expf(Sacc[mt][nt][1] * SC - mn0);
                float p2 = __expf(Sacc[mt][nt][2] * SC - mn1);
                float p3 = __expf(Sacc[mt][nt][3] * SC - mn1);
                rs0 += p0 + p1; rs1 += p2 + p3;
                pa[mt][nt][0] = packbf(p0, p1);
                pa[mt][nt][1] = packbf(p2, p3);
            }
            rs0 += __shfl_xor_sync(0xffffffffu, rs0, 1);
            rs0 += __shfl_xor_sync(0xffffffffu, rs0, 2);
            rs1 += __shfl_xor_sync(0xffffffffu, rs1, 1);
            rs1 += __shfl_xor_sync(0xffffffffu, rs1, 2);
            l_i[mt * 2]     = l_i[mt * 2] * al0 + rs0;
            l_i[mt * 2 + 1] = l_i[mt * 2 + 1] * al1 + rs1;
            m_i[mt * 2] = mn0; m_i[mt * 2 + 1] = mn1;
            #pragma unroll
            for (int ct = 0; ct < 8; ct++) {
                Oacc[mt][ct][0] *= al0; Oacc[mt][ct][1] *= al0;
                Oacc[mt][ct][2] *= al1; Oacc[mt][ct][3] *= al1;
            }
        }

        // O += P @ V^T
        #pragma unroll
        for (int ksi = 0; ksi < 4; ksi++) {
            uint32_t vb[4][4];
            #pragma unroll
            for (int p = 0; p < 4; p++) {
                int row = p * 16 + (grp >> 1) * 8 + r8;
                int col = ksi * 16 + (grp & 1) * 8;
                ldsm4(vb[p], saddr(vs + row * KSTR + col));
            }
            #pragma unroll
            for (int mt = 0; mt < 2; mt++) {
                uint32_t af[4] = { pa[mt][2 * ksi][0],     pa[mt][2 * ksi][1],
                                   pa[mt][2 * ksi + 1][0], pa[mt][2 * ksi + 1][1] };
                #pragma unroll
                for (int p = 0; p < 4; p++) {
                    mma_bf16(Oacc[mt][2 * p],     af, &vb[p][0]);
                    mma_bf16(Oacc[mt][2 * p + 1], af, &vb[p][2]);
                }
            }
        }
        __syncthreads();
    }

    // Normalize, transpose via smem (reuse qs as [c][t] bf16), store bf16.
    uint16_t* osm = qs;
    #pragma unroll
    for (int mt = 0; mt < 2; mt++) {
        float inv0 = 1.f / l_i[mt * 2], inv1 = 1.f / l_i[mt * 2 + 1];
        int t = warp * 32 + mt * 16 + g;
        #pragma unroll
        for (int ct = 0; ct < 8; ct++) {
            int c = (ct >> 1) * 16 + (ct & 1) * 8 + 2 * tg;
            uint32_t u0 = packbf(Oacc[mt][ct][0] * inv0, Oacc[mt][ct][1] * inv0);
            uint32_t u1 = packbf(Oacc[mt][ct][2] * inv1, Oacc[mt][ct][3] * inv1);
            osm[(c + 0) * QSTR + t] = (uint16_t)(u0 & 0xffff);
            osm[(c + 1) * QSTR + t] = (uint16_t)(u0 >> 16);
            osm[(c + 0) * QSTR + t + 8] = (uint16_t)(u1 & 0xffff);
            osm[(c + 1) * QSTR + t + 8] = (uint16_t)(u1 >> 16);
        }
    }
    __syncthreads();
    size_t obase = ((size_t)b * C_ + (size_t)hh * CH_) * L_ + t0;
    #pragma unroll
    for (int i = 0; i < 8; i++) {
        int id = tid + 128 * i, row = id >> 4, seg = id & 15;
        uint4 v = *(uint4*)(osm + row * QSTR + seg * 8);
        *(uint4*)(outa + obase + (size_t)row * L_ + seg * 8) = v;
    }
}

// ---------------------------------------------------------------------------
// Launch
// ---------------------------------------------------------------------------
extern "C" void kernel_launch(void* const* d_in, const int* in_sizes, int n_in,
                              void* d_out, int out_size)
{
    const float* x      = (const float*)d_in[0];
    const float* enc    = (const float*)d_in[1];
    const float* gnsc   = (const float*)d_in[2];
    const float* gnbi   = (const float*)d_in[3];
    const float* w_qkv  = (const float*)d_in[4];
    const float* b_qkv  = (const float*)d_in[5];
    const float* w_ekv  = (const float*)d_in[6];
    const float* b_ekv  = (const float*)d_in[7];
    const float* w_proj = (const float*)d_in[8];
    const float* b_proj = (const float*)d_in[9];
    float* out = (float*)d_out;

    __nv_bfloat16 *h, *qkv, *ekvb, *a, *wqkv, *wekv, *wproj, *encb;
    cudaGetSymbolAddress((void**)&h,     gb_h);
    cudaGetSymbolAddress((void**)&qkv,   gb_qkv);
    cudaGetSymbolAddress((void**)&ekvb,  gb_ekv);
    cudaGetSymbolAddress((void**)&a,     gb_a);
    cudaGetSymbolAddress((void**)&wqkv,  gb_wqkv);
    cudaGetSymbolAddress((void**)&wekv,  gb_wekv);
    cudaGetSymbolAddress((void**)&wproj, gb_wproj);
    cudaGetSymbolAddress((void**)&encb,  gb_enc);

    const int GN_SMEM = CPG * L_ * 4;   // 65536
    cudaFuncSetAttribute(gn_kernel, cudaFuncAttributeMaxDynamicSharedMemorySize, GN_SMEM);
    cudaFuncSetAttribute(attn_tc, cudaFuncAttributeMaxDynamicSharedMemorySize, ATTN_SMEM);

    // 0. Convert weights + encoder to bf16
    cvt_kernel<<<(3 * C_ * C_ / 4 + 255) / 256, 256>>>((const float4*)w_qkv,  (uint2*)wqkv,  3 * C_ * C_ / 4);
    cvt_kernel<<<(2 * C_ * EC_ / 4 + 255) / 256, 256>>>((const float4*)w_ekv,  (uint2*)wekv,  2 * C_ * EC_ / 4);
    cvt_kernel<<<(C_ * C_ / 4 + 255) / 256, 256>>>((const float4*)w_proj, (uint2*)wproj, C_ * C_ / 4);
    cvt_kernel<<<(B_ * EC_ * LE_ / 4 + 255) / 256, 256>>>((const float4*)enc, (uint2*)encb, B_ * EC_ * LE_ / 4);

    // 1. GroupNorm -> bf16 h
    gn_kernel<<<B_ * G_, 256, GN_SMEM>>>(x, gnsc, gnbi, h);

    // 2. qkv = w_qkv @ h + b_qkv -> bf16   (M=1536, N=1024, K=512)
    gemm_cp<false, true><<<dim3(L_ / 128, 3 * C_ / 128, B_), 256>>>(
        wqkv, h, b_qkv, nullptr, qkv, 3 * C_, L_, C_);

    // 3. ekv = w_ekv @ enc + b_ekv -> bf16 (M=1024, N=128, K=512)
    gemm_cp<false, true><<<dim3(LE_ / 128, 2 * C_ / 128, B_), 256>>>(
        wekv, encb, b_ekv, nullptr, ekvb, 2 * C_, LE_, EC_);

    // 4. attention -> bf16 a
    attn_tc<<<dim3(L_ / 128, B_ * H_), 128, ATTN_SMEM>>>(qkv, ekvb, a);

    // 5. out = x + w_proj @ a + b_proj (fp32 out)
    gemm_cp<true, false><<<dim3(L_ / 128, C_ / 128, B_), 256>>>(
        wproj, a, b_proj, x, out, C_, L_, C_);
}